// round 2
// baseline (speedup 1.0000x reference)
#include <cuda_runtime.h>
#include <cuda_bf16.h>

#define BB  8
#define QQ  32
#define LEN 128
#define DD  512
#define PP  32
#define AA  128

// Scratch (device globals: allocation-free, graph-capturable)
__device__ float g_ws[BB*PP*AA];          // (B,P,A)
__device__ float g_uh[BB*QQ*LEN*AA];      // (B,Q,LE,A)  16 MB
__device__ float g_e [BB*PP*QQ*LEN];      // (B,P,Q,LE)   4 MB (e, then a in-place)

__device__ __forceinline__ float tanh_fast(float x){
    float y; asm("tanh.approx.f32 %0, %1;" : "=f"(y) : "f"(x)); return y;
}
__device__ __forceinline__ unsigned long long pk2(float lo, float hi){
    unsigned long long r; asm("mov.b64 %0, {%1,%2};" : "=l"(r) : "f"(lo), "f"(hi)); return r;
}
__device__ __forceinline__ void upk2(unsigned long long v, float& lo, float& hi){
    asm("mov.b64 {%0,%1}, %2;" : "=f"(lo), "=f"(hi) : "l"(v));
}
__device__ __forceinline__ unsigned long long fma2(unsigned long long a,
                                                   unsigned long long b,
                                                   unsigned long long c){
    unsigned long long d;
    asm("fma.rn.f32x2 %0, %1, %2, %3;" : "=l"(d) : "l"(a), "l"(b), "l"(c));
    return d;
}

// ---------------------------------------------------------------------------
// K1: ws[b,p,a] = dot(s_j[b,p,:], Ws_w[a,:]) + Ws_b[a]
// grid = B*P, block = 128 (one thread per a)
// ---------------------------------------------------------------------------
__global__ void __launch_bounds__(128) k_ws(const float* __restrict__ s_j,
                                            const float* __restrict__ Ws_w,
                                            const float* __restrict__ Ws_b){
    __shared__ float sj[DD];
    const int bp  = blockIdx.x;
    const int tid = threadIdx.x;
    *(float4*)&sj[tid*4] = *(const float4*)(s_j + (size_t)bp*DD + tid*4);
    __syncthreads();
    float acc = 0.0f;
    const float* wr = Ws_w + (size_t)tid*DD;
    #pragma unroll 8
    for (int d = 0; d < DD; d += 4){
        float4 w = *(const float4*)(wr + d);
        float4 s = *(const float4*)&sj[d];
        acc += w.x*s.x + w.y*s.y + w.z*s.z + w.w*s.w;
    }
    g_ws[bp*AA + tid] = acc + Ws_b[tid];
}

// ---------------------------------------------------------------------------
// K2: uh = X(32768x512) @ U^T(512x128), fp32 via packed f32x2 FMA.
// Block tile 128(M) x 128(N), BK=16, 256 threads, 8x8 micro-tile (interleaved).
// grid = 256
// ---------------------------------------------------------------------------
__global__ void __launch_bounds__(256) k_uh(const float* __restrict__ X,
                                            const float* __restrict__ U){
    __shared__ float As[16][128];   // [k][m]
    __shared__ float Bs[16][128];   // [k][n]
    const int m0  = blockIdx.x * 128;
    const int tid = threadIdx.x;
    const int tx  = tid & 15, ty = tid >> 4;

    unsigned long long acc2[8][4];
    #pragma unroll
    for (int i = 0; i < 8; i++)
        #pragma unroll
        for (int j = 0; j < 4; j++) acc2[i][j] = 0ull;

    for (int k0 = 0; k0 < DD; k0 += 16){
        #pragma unroll
        for (int i = 0; i < 2; i++){
            int idx = tid*2 + i;            // 0..511
            int row = idx >> 2;             // 0..127
            int kq  = (idx & 3) * 4;        // 0,4,8,12
            float4 vX = *(const float4*)(X + (size_t)(m0+row)*DD + k0 + kq);
            As[kq+0][row]=vX.x; As[kq+1][row]=vX.y; As[kq+2][row]=vX.z; As[kq+3][row]=vX.w;
            float4 vU = *(const float4*)(U + (size_t)row*DD + k0 + kq);
            Bs[kq+0][row]=vU.x; Bs[kq+1][row]=vU.y; Bs[kq+2][row]=vU.z; Bs[kq+3][row]=vU.w;
        }
        __syncthreads();
        #pragma unroll
        for (int k = 0; k < 16; k++){
            float4 a0 = *(const float4*)&As[k][ty*4];
            float4 a1 = *(const float4*)&As[k][ty*4 + 64];
            ulonglong2 b0 = *(const ulonglong2*)&Bs[k][tx*4];
            ulonglong2 b1 = *(const ulonglong2*)&Bs[k][tx*4 + 64];
            float am[8] = {a0.x,a0.y,a0.z,a0.w,a1.x,a1.y,a1.z,a1.w};
            unsigned long long bn[4] = {b0.x,b0.y,b1.x,b1.y};
            #pragma unroll
            for (int i = 0; i < 8; i++){
                unsigned long long ai = pk2(am[i], am[i]);
                #pragma unroll
                for (int j = 0; j < 4; j++)
                    acc2[i][j] = fma2(ai, bn[j], acc2[i][j]);
            }
        }
        __syncthreads();
    }
    float* outp = g_uh + (size_t)m0 * AA;
    #pragma unroll
    for (int i = 0; i < 8; i++){
        int m = ty*4 + (i & 3) + (i >> 2) * 64;
        #pragma unroll
        for (int jh = 0; jh < 2; jh++){
            float x0,x1,x2,x3;
            upk2(acc2[i][jh*2+0], x0, x1);
            upk2(acc2[i][jh*2+1], x2, x3);
            int n = tx*4 + jh*64;
            *(float4*)(outp + (size_t)m*AA + n) = make_float4(x0,x1,x2,x3);
        }
    }
}

// ---------------------------------------------------------------------------
// K3: e[b,p,q,t] = sum_a tanh(uh[b,q,t,a] + ws[b,p,a]) * v[a]  (+mask)
// grid = (Q, B), 256 threads; thread tile 4p x 4t; a vectorized (float4).
// smem rows padded to 132 floats -> word-stride 33 (==1 mod 8): conflict-free.
// ---------------------------------------------------------------------------
__global__ void __launch_bounds__(256) k_score(const int*   __restrict__ exp_mask,
                                               const float* __restrict__ v_w){
    extern __shared__ float sm[];
    float* uh_s = sm;                    // 128*132
    float* ws_s = sm + 128*132;          // 32*132
    float* v_s  = ws_s + 32*132;         // 128
    int*   mk_s = (int*)(v_s + 128);     // 128
    const int q = blockIdx.x, b = blockIdx.y;
    const int tid = threadIdx.x;
    const int tx = tid & 31, ty = tid >> 5;
    const int bq = b*QQ + q;

    const float* uhg = g_uh + (size_t)bq * LEN * AA;
    #pragma unroll
    for (int i = 0; i < 16; i++){
        int idx = tid + i*256;                 // float4 idx 0..4095
        int t = idx >> 5;
        int a = (idx & 31) * 4;
        *(float4*)&uh_s[t*132 + a] = *(const float4*)(uhg + t*AA + a);
    }
    const float* wsg = g_ws + b * PP * AA;
    #pragma unroll
    for (int i = 0; i < 4; i++){
        int idx = tid + i*256;                 // 0..1023
        int p = idx >> 5;
        int a = (idx & 31) * 4;
        *(float4*)&ws_s[p*132 + a] = *(const float4*)(wsg + p*AA + a);
    }
    if (tid < 32)  *(float4*)&v_s[tid*4] = *(const float4*)(v_w + tid*4);
    if (tid < 128) mk_s[tid] = exp_mask[bq*LEN + tid];
    __syncthreads();

    const int p0 = ty * 4;
    float acc[4][4];
    #pragma unroll
    for (int i = 0; i < 4; i++)
        #pragma unroll
        for (int j = 0; j < 4; j++) acc[i][j] = 0.0f;

    for (int a0 = 0; a0 < AA; a0 += 4){
        float4 v4 = *(const float4*)&v_s[a0];
        float4 w[4], u[4];
        #pragma unroll
        for (int i = 0; i < 4; i++) w[i] = *(const float4*)&ws_s[(p0+i)*132 + a0];
        #pragma unroll
        for (int j = 0; j < 4; j++) u[j] = *(const float4*)&uh_s[(tx + 32*j)*132 + a0];
        #pragma unroll
        for (int i = 0; i < 4; i++){
            #pragma unroll
            for (int j = 0; j < 4; j++){
                float s;
                s  = tanh_fast(u[j].x + w[i].x) * v4.x;
                s += tanh_fast(u[j].y + w[i].y) * v4.y;
                s += tanh_fast(u[j].z + w[i].z) * v4.z;
                s += tanh_fast(u[j].w + w[i].w) * v4.w;
                acc[i][j] += s;
            }
        }
    }
    #pragma unroll
    for (int i = 0; i < 4; i++){
        float* er = g_e + (((size_t)(b*PP + p0 + i))*QQ + q) * LEN;
        #pragma unroll
        for (int j = 0; j < 4; j++){
            int t = tx + 32*j;
            er[t] = mk_s[t] ? acc[i][j] : -1.0e9f;
        }
    }
}

// ---------------------------------------------------------------------------
// K4: softmax over rows of 4096 (in-place on g_e). grid = B*P, 256 threads.
// ---------------------------------------------------------------------------
__global__ void __launch_bounds__(256) k_softmax(){
    __shared__ float red[8];
    __shared__ float bcast;
    const int bp  = blockIdx.x;
    float* row = g_e + (size_t)bp * (QQ*LEN);
    const int tid  = threadIdx.x;
    const int lane = tid & 31, warp = tid >> 5;

    float4 v[4];
    #pragma unroll
    for (int i = 0; i < 4; i++) v[i] = *(const float4*)&row[(tid + i*256)*4];

    float mx = -3.0e38f;
    #pragma unroll
    for (int i = 0; i < 4; i++)
        mx = fmaxf(mx, fmaxf(fmaxf(v[i].x, v[i].y), fmaxf(v[i].z, v[i].w)));
    #pragma unroll
    for (int o = 16; o; o >>= 1) mx = fmaxf(mx, __shfl_xor_sync(0xffffffffu, mx, o));
    if (lane == 0) red[warp] = mx;
    __syncthreads();
    if (tid == 0){
        float m = red[0];
        #pragma unroll
        for (int i = 1; i < 8; i++) m = fmaxf(m, red[i]);
        bcast = m;
    }
    __syncthreads();
    mx = bcast;

    float s = 0.0f;
    #pragma unroll
    for (int i = 0; i < 4; i++){
        v[i].x = __expf(v[i].x - mx); v[i].y = __expf(v[i].y - mx);
        v[i].z = __expf(v[i].z - mx); v[i].w = __expf(v[i].w - mx);
        s += v[i].x + v[i].y + v[i].z + v[i].w;
    }
    #pragma unroll
    for (int o = 16; o; o >>= 1) s += __shfl_xor_sync(0xffffffffu, s, o);
    if (lane == 0) red[warp] = s;
    __syncthreads();
    if (tid == 0){
        float t = 0.0f;
        #pragma unroll
        for (int i = 0; i < 8; i++) t += red[i];
        bcast = 1.0f / t;
    }
    __syncthreads();
    const float inv = bcast;
    #pragma unroll
    for (int i = 0; i < 4; i++){
        v[i].x *= inv; v[i].y *= inv; v[i].z *= inv; v[i].w *= inv;
        *(float4*)&row[(tid + i*256)*4] = v[i];
    }
}

// ---------------------------------------------------------------------------
// K5: out[b,q,p,d] = (sum_t a[b,p,q,t] * X[b,q,t,d]) * req_mask[b,p]
// grid = (Q, B), 256 threads; 4p x 16d per thread, t in chunks of 32; f32x2.
// ---------------------------------------------------------------------------
__global__ void __launch_bounds__(256) k_out(const float* __restrict__ X,
                                             const int*   __restrict__ req_mask,
                                             float* __restrict__ out){
    extern __shared__ float sm[];
    float* Xs   = sm;                  // 32*512
    float* a_s  = sm + 32*512;         // 32*132
    float* rm_s = a_s + 32*132;        // 32
    const int q = blockIdx.x, b = blockIdx.y;
    const int tid = threadIdx.x;
    const int tx = tid & 31, ty = tid >> 5;
    const int bq = b*QQ + q;
    const int p0 = ty * 4;

    #pragma unroll
    for (int i = 0; i < 4; i++){
        int idx = tid + i*256;               // 0..1023
        int p = idx >> 5;
        int t = (idx & 31) * 4;
        *(float4*)&a_s[p*132 + t] =
            *(const float4*)(g_e + (((size_t)(b*PP + p))*QQ + q)*LEN + t);
    }
    if (tid < 32) rm_s[tid] = (float)req_mask[b*PP + tid];

    unsigned long long acc2[4][8];
    #pragma unroll
    for (int i = 0; i < 4; i++)
        #pragma unroll
        for (int j = 0; j < 8; j++) acc2[i][j] = 0ull;

    const float* Xg = X + (size_t)bq * LEN * DD;
    for (int c = 0; c < 4; c++){
        __syncthreads();  // a_s/rm_s visible (c==0); Xs free of readers (c>0)
        #pragma unroll
        for (int i = 0; i < 16; i++){
            int idx = tid + i*256;           // float4 idx 0..4095
            int r  = idx >> 7;               // 0..31
            int wv = (idx & 127) * 4;
            *(float4*)&Xs[r*512 + wv] =
                *(const float4*)(Xg + (size_t)(c*32 + r)*DD + wv);
        }
        __syncthreads();
        #pragma unroll
        for (int tt = 0; tt < 32; tt++){
            const int t = c*32 + tt;
            unsigned long long a2[4];
            #pragma unroll
            for (int i = 0; i < 4; i++){
                float av = a_s[(p0+i)*132 + t];
                a2[i] = pk2(av, av);
            }
            #pragma unroll
            for (int j = 0; j < 4; j++){
                ulonglong2 x2 = *(const ulonglong2*)&Xs[tt*512 + (tx + 32*j)*4];
                #pragma unroll
                for (int i = 0; i < 4; i++){
                    acc2[i][2*j]   = fma2(a2[i], x2.x, acc2[i][2*j]);
                    acc2[i][2*j+1] = fma2(a2[i], x2.y, acc2[i][2*j+1]);
                }
            }
        }
    }
    float* og = out + (size_t)bq * PP * DD;
    #pragma unroll
    for (int i = 0; i < 4; i++){
        float r = rm_s[p0 + i];
        #pragma unroll
        for (int j = 0; j < 4; j++){
            float x0,x1,x2,x3;
            upk2(acc2[i][2*j],   x0, x1);
            upk2(acc2[i][2*j+1], x2, x3);
            *(float4*)(og + (size_t)(p0+i)*DD + (tx + 32*j)*4) =
                make_float4(x0*r, x1*r, x2*r, x3*r);
        }
    }
}

// ---------------------------------------------------------------------------
extern "C" void kernel_launch(void* const* d_in, const int* in_sizes, int n_in,
                              void* d_out, int out_size){
    const float* exp_tokens = (const float*)d_in[0];
    const int*   exp_mask   = (const int*)  d_in[1];
    const float* s_j        = (const float*)d_in[2];
    const int*   req_mask   = (const int*)  d_in[3];
    const float* Ws_w       = (const float*)d_in[4];
    const float* Ws_b       = (const float*)d_in[5];
    const float* U_w        = (const float*)d_in[6];
    const float* v_w        = (const float*)d_in[7];
    float* out = (float*)d_out;

    const int smem_score = (128*132 + 32*132 + 128)*4 + 128*4;   // 85504 B
    const int smem_out   = (32*512 + 32*132 + 32)*4;             // 82560 B
    cudaFuncSetAttribute(k_score, cudaFuncAttributeMaxDynamicSharedMemorySize, smem_score);
    cudaFuncSetAttribute(k_out,   cudaFuncAttributeMaxDynamicSharedMemorySize, smem_out);

    k_ws     <<<BB*PP, 128>>>(s_j, Ws_w, Ws_b);
    k_uh     <<<(BB*QQ*LEN)/128, 256>>>(exp_tokens, U_w);
    k_score  <<<dim3(QQ, BB), 256, smem_score>>>(exp_mask, v_w);
    k_softmax<<<BB*PP, 256>>>();
    k_out    <<<dim3(QQ, BB), 256, smem_out>>>(exp_tokens, req_mask, out);
}

// round 4
// speedup vs baseline: 1.4406x; 1.4406x over previous
#include <cuda_runtime.h>
#include <cuda_bf16.h>
#include <cstdint>

#define BB  8
#define QQ  32
#define LEN 128
#define DD  512
#define PP  32
#define AA  128

// Scratch (device globals: allocation-free, graph-capturable)
__device__ float g_ws[BB*PP*AA];                 // (B,P,A)
__device__ float g_uh[BB*QQ*LEN*AA];             // (B,Q,LE,A)  16 MB
__device__ float g_e [BB*PP*QQ*LEN];             // (B,P,Q,LE)   4 MB
__device__ __nv_bfloat16 g_Uh[AA*DD];            // U hi split (bf16)
__device__ __nv_bfloat16 g_Ul[AA*DD];            // U lo split (bf16)

// ---------------------------------------------------------------------------
// helpers
// ---------------------------------------------------------------------------
__device__ __forceinline__ float tanh_fast(float x){
    float y; asm("tanh.approx.f32 %0, %1;" : "=f"(y) : "f"(x)); return y;
}
__device__ __forceinline__ unsigned long long pk2(float lo, float hi){
    unsigned long long r; asm("mov.b64 %0, {%1,%2};" : "=l"(r) : "f"(lo), "f"(hi)); return r;
}
__device__ __forceinline__ void upk2(unsigned long long v, float& lo, float& hi){
    asm("mov.b64 {%0,%1}, %2;" : "=f"(lo), "=f"(hi) : "l"(v));
}
__device__ __forceinline__ unsigned long long fma2(unsigned long long a,
                                                   unsigned long long b,
                                                   unsigned long long c){
    unsigned long long d;
    asm("fma.rn.f32x2 %0, %1, %2, %3;" : "=l"(d) : "l"(a), "l"(b), "l"(c));
    return d;
}
__device__ __forceinline__ uint32_t smem_u32(const void* p){
    uint32_t a;
    asm("{ .reg .u64 t; cvta.to.shared.u64 t, %1; cvt.u32.u64 %0, t; }" : "=r"(a) : "l"(p));
    return a;
}
__device__ __forceinline__ uint32_t bf2u(__nv_bfloat162 v){
    return *reinterpret_cast<uint32_t*>(&v);
}
// sm_80+ primitives (valid at target sm_103)
__device__ __forceinline__ void ldsm4(uint32_t* r, uint32_t a){
    asm volatile("ldmatrix.sync.aligned.m8n8.x4.shared.b16 {%0,%1,%2,%3}, [%4];"
        : "=r"(r[0]), "=r"(r[1]), "=r"(r[2]), "=r"(r[3]) : "r"(a));
}
__device__ __forceinline__ void mma_bf16(float* c, const uint32_t* a, const uint32_t* b){
    asm volatile("mma.sync.aligned.m16n8k16.row.col.f32.bf16.bf16.f32 "
        "{%0,%1,%2,%3}, {%4,%5,%6,%7}, {%8,%9}, {%0,%1,%2,%3};"
        : "+f"(c[0]), "+f"(c[1]), "+f"(c[2]), "+f"(c[3])
        : "r"(a[0]), "r"(a[1]), "r"(a[2]), "r"(a[3]), "r"(b[0]), "r"(b[1]));
}
__device__ __forceinline__ void cp16(uint32_t d, const void* s){
    asm volatile("cp.async.cg.shared.global [%0], [%1], 16;" :: "r"(d), "l"(s));
}
#define CP_COMMIT() asm volatile("cp.async.commit_group;" ::: "memory")
#define CP_WAIT0()  asm volatile("cp.async.wait_group 0;" ::: "memory")

// ---------------------------------------------------------------------------
// K0: split U (fp32) into bf16 hi/lo parts. grid=64, block=256.
// ---------------------------------------------------------------------------
__global__ void __launch_bounds__(256) k_prep_u(const float* __restrict__ U){
    int idx = (blockIdx.x * 256 + threadIdx.x) * 4;
    float4 v = *(const float4*)(U + idx);
    __nv_bfloat16 hx = __float2bfloat16(v.x), hy = __float2bfloat16(v.y);
    __nv_bfloat16 hz = __float2bfloat16(v.z), hw = __float2bfloat16(v.w);
    __nv_bfloat162 h01 = __halves2bfloat162(hx, hy);
    __nv_bfloat162 h23 = __halves2bfloat162(hz, hw);
    __nv_bfloat162 l01 = __floats2bfloat162_rn(v.x - __bfloat162float(hx),
                                               v.y - __bfloat162float(hy));
    __nv_bfloat162 l23 = __floats2bfloat162_rn(v.z - __bfloat162float(hz),
                                               v.w - __bfloat162float(hw));
    *(__nv_bfloat162*)(g_Uh + idx)     = h01;
    *(__nv_bfloat162*)(g_Uh + idx + 2) = h23;
    *(__nv_bfloat162*)(g_Ul + idx)     = l01;
    *(__nv_bfloat162*)(g_Ul + idx + 2) = l23;
}

// ---------------------------------------------------------------------------
// K1: ws[b,p,a] = dot(s_j[b,p,:], Ws_w[a,:]) + Ws_b[a]
// ---------------------------------------------------------------------------
__global__ void __launch_bounds__(128) k_ws(const float* __restrict__ s_j,
                                            const float* __restrict__ Ws_w,
                                            const float* __restrict__ Ws_b){
    __shared__ float sj[DD];
    const int bp  = blockIdx.x;
    const int tid = threadIdx.x;
    *(float4*)&sj[tid*4] = *(const float4*)(s_j + (size_t)bp*DD + tid*4);
    __syncthreads();
    float acc = 0.0f;
    const float* wr = Ws_w + (size_t)tid*DD;
    #pragma unroll 8
    for (int d = 0; d < DD; d += 4){
        float4 w = *(const float4*)(wr + d);
        float4 s = *(const float4*)&sj[d];
        acc += w.x*s.x + w.y*s.y + w.z*s.z + w.w*s.w;
    }
    g_ws[bp*AA + tid] = acc + Ws_b[tid];
}

// ---------------------------------------------------------------------------
// K2: uh = X(32768x512) @ U^T via mma.sync bf16 (3-term split XhUh+XhUl+XlUh).
// CTA: 128(M) x 128(N), 512 threads (4x4 warp grid, 32x32 per warp).
// K chunks of 64, double-buffered smem. Rows padded to 144B (conflict-free
// ldmatrix: 8 rows at word offsets 0,36,..,252 mod 32 cover all banks once).
// ---------------------------------------------------------------------------
#define XROWB 144                    // padded row bytes (72 bf16)
#define TILEB (128*XROWB)            // 18432 B per operand tile
#define CHUNKB (4*TILEB)             // Xh,Xl,Uh,Ul
#define UHMMA_SMEM (2*CHUNKB)        // 147456 B

__global__ void __launch_bounds__(512) k_uh_mma(const float* __restrict__ X){
    extern __shared__ char sm[];
    const uint32_t sb = smem_u32(sm);
    const int tid  = threadIdx.x;
    const int lane = tid & 31, wid = tid >> 5;
    const int warp_m = wid & 3;          // 0..3 -> 32 M rows
    const int warp_n = wid >> 2;         // 0..3 -> 32 N cols
    const int m0 = blockIdx.x * 128;

    float acc[2][4][4];
    #pragma unroll
    for (int a = 0; a < 2; a++)
        #pragma unroll
        for (int b = 0; b < 4; b++)
            #pragma unroll
            for (int c = 0; c < 4; c++) acc[a][b][c] = 0.0f;

    float4 xr[4];

    // ---- prologue: chunk 0 ----
    #pragma unroll
    for (int j = 0; j < 4; j++){
        int idx = tid + j*512;
        int row = idx >> 4, k4 = (idx & 15) * 4;
        xr[j] = *(const float4*)(X + (size_t)(m0+row)*DD + k4);
    }
    #pragma unroll
    for (int j = 0; j < 2; j++){
        int idx = tid + j*512;
        int row = idx >> 3, seg = idx & 7;
        uint32_t off = (uint32_t)row*XROWB + seg*16;
        cp16(sb + 2*TILEB + off, g_Uh + (size_t)row*DD + seg*8);
        cp16(sb + 3*TILEB + off, g_Ul + (size_t)row*DD + seg*8);
    }
    CP_COMMIT();
    #pragma unroll
    for (int j = 0; j < 4; j++){
        int idx = tid + j*512;
        int row = idx >> 4, k4 = (idx & 15) * 4;
        float4 v = xr[j];
        __nv_bfloat16 hx = __float2bfloat16(v.x), hy = __float2bfloat16(v.y);
        __nv_bfloat16 hz = __float2bfloat16(v.z), hw = __float2bfloat16(v.w);
        uint2 h = make_uint2(bf2u(__halves2bfloat162(hx, hy)),
                             bf2u(__halves2bfloat162(hz, hw)));
        uint2 l = make_uint2(bf2u(__floats2bfloat162_rn(v.x - __bfloat162float(hx),
                                                        v.y - __bfloat162float(hy))),
                             bf2u(__floats2bfloat162_rn(v.z - __bfloat162float(hz),
                                                        v.w - __bfloat162float(hw))));
        uint32_t off = (uint32_t)row*XROWB + (uint32_t)k4*2;
        *(uint2*)(sm + off)         = h;
        *(uint2*)(sm + TILEB + off) = l;
    }
    CP_WAIT0();
    __syncthreads();

    // precomputed fragment addresses (relative to tile base)
    const uint32_t a_base = (uint32_t)(warp_m*32 + (lane & 15))*XROWB + ((lane >> 4) << 4);
    const uint32_t b_base = (uint32_t)(warp_n*32 + (lane & 7) + ((lane >> 4) << 3))*XROWB
                          + (((lane >> 3) & 1) << 4);

    for (int c = 0; c < DD/64; c++){
        const uint32_t boff = (uint32_t)(c & 1) * CHUNKB;
        const uint32_t noff = boff ^ CHUNKB;
        const int k0n = (c+1) * 64;
        if (c < 7){
            #pragma unroll
            for (int j = 0; j < 4; j++){
                int idx = tid + j*512;
                int row = idx >> 4, k4 = (idx & 15) * 4;
                xr[j] = *(const float4*)(X + (size_t)(m0+row)*DD + k0n + k4);
            }
            #pragma unroll
            for (int j = 0; j < 2; j++){
                int idx = tid + j*512;
                int row = idx >> 3, seg = idx & 7;
                uint32_t off = (uint32_t)row*XROWB + seg*16;
                cp16(sb + noff + 2*TILEB + off, g_Uh + (size_t)row*DD + k0n + seg*8);
                cp16(sb + noff + 3*TILEB + off, g_Ul + (size_t)row*DD + k0n + seg*8);
            }
            CP_COMMIT();
        }
        // ---- compute on buf ----
        const uint32_t xh = sb + boff, xl = xh + TILEB;
        const uint32_t uh = xh + 2*TILEB, ul = xh + 3*TILEB;
        #pragma unroll
        for (int ks = 0; ks < 4; ks++){
            const uint32_t kb = (uint32_t)ks * 32;
            uint32_t ah[2][4], al[2][4];
            ldsm4(ah[0], xh + a_base + kb);
            ldsm4(ah[1], xh + a_base + kb + 16*XROWB);
            ldsm4(al[0], xl + a_base + kb);
            ldsm4(al[1], xl + a_base + kb + 16*XROWB);
            uint32_t bh[4][2], bl[4][2];
            #pragma unroll
            for (int g = 0; g < 2; g++){
                uint32_t t0[4], t1[4];
                ldsm4(t0, uh + b_base + kb + (uint32_t)g*16*XROWB);
                ldsm4(t1, ul + b_base + kb + (uint32_t)g*16*XROWB);
                bh[2*g][0]=t0[0]; bh[2*g][1]=t0[1]; bh[2*g+1][0]=t0[2]; bh[2*g+1][1]=t0[3];
                bl[2*g][0]=t1[0]; bl[2*g][1]=t1[1]; bl[2*g+1][0]=t1[2]; bl[2*g+1][1]=t1[3];
            }
            #pragma unroll
            for (int mt = 0; mt < 2; mt++){
                #pragma unroll
                for (int nt = 0; nt < 4; nt++){
                    mma_bf16(acc[mt][nt], ah[mt], bh[nt]);
                    mma_bf16(acc[mt][nt], ah[mt], bl[nt]);
                    mma_bf16(acc[mt][nt], al[mt], bh[nt]);
                }
            }
        }
        if (c < 7){
            #pragma unroll
            for (int j = 0; j < 4; j++){
                int idx = tid + j*512;
                int row = idx >> 4, k4 = (idx & 15) * 4;
                float4 v = xr[j];
                __nv_bfloat16 hx = __float2bfloat16(v.x), hy = __float2bfloat16(v.y);
                __nv_bfloat16 hz = __float2bfloat16(v.z), hw = __float2bfloat16(v.w);
                uint2 h = make_uint2(bf2u(__halves2bfloat162(hx, hy)),
                                     bf2u(__halves2bfloat162(hz, hw)));
                uint2 l = make_uint2(bf2u(__floats2bfloat162_rn(v.x - __bfloat162float(hx),
                                                                v.y - __bfloat162float(hy))),
                                     bf2u(__floats2bfloat162_rn(v.z - __bfloat162float(hz),
                                                                v.w - __bfloat162float(hw))));
                uint32_t off = (noff) + (uint32_t)row*XROWB + (uint32_t)k4*2;
                *(uint2*)(sm + off)         = h;
                *(uint2*)(sm + TILEB + off) = l;
            }
            CP_WAIT0();
        }
        __syncthreads();
    }

    // ---- epilogue ----
    const int r = lane >> 2, cp2 = (lane & 3) * 2;
    float* base = g_uh + (size_t)(m0 + warp_m*32) * AA + warp_n*32;
    #pragma unroll
    for (int mt = 0; mt < 2; mt++){
        #pragma unroll
        for (int nt = 0; nt < 4; nt++){
            float* p0 = base + (size_t)(mt*16 + r) * AA + nt*8 + cp2;
            float* p1 = base + (size_t)(mt*16 + r + 8) * AA + nt*8 + cp2;
            *(float2*)p0 = make_float2(acc[mt][nt][0], acc[mt][nt][1]);
            *(float2*)p1 = make_float2(acc[mt][nt][2], acc[mt][nt][3]);
        }
    }
}

// ---------------------------------------------------------------------------
// K3: e[b,p,q,t] = sum_a tanh(uh[b,q,t,a] + ws[b,p,a]) * v[a]  (+mask)
// ---------------------------------------------------------------------------
__global__ void __launch_bounds__(256) k_score(const int*   __restrict__ exp_mask,
                                               const float* __restrict__ v_w){
    extern __shared__ float smf[];
    float* uh_s = smf;                   // 128*132
    float* ws_s = smf + 128*132;         // 32*132
    float* v_s  = ws_s + 32*132;         // 128
    int*   mk_s = (int*)(v_s + 128);     // 128
    const int q = blockIdx.x, b = blockIdx.y;
    const int tid = threadIdx.x;
    const int tx = tid & 31, ty = tid >> 5;
    const int bq = b*QQ + q;

    const float* uhg = g_uh + (size_t)bq * LEN * AA;
    #pragma unroll
    for (int i = 0; i < 16; i++){
        int idx = tid + i*256;
        int t = idx >> 5;
        int a = (idx & 31) * 4;
        *(float4*)&uh_s[t*132 + a] = *(const float4*)(uhg + t*AA + a);
    }
    const float* wsg = g_ws + b * PP * AA;
    #pragma unroll
    for (int i = 0; i < 4; i++){
        int idx = tid + i*256;
        int p = idx >> 5;
        int a = (idx & 31) * 4;
        *(float4*)&ws_s[p*132 + a] = *(const float4*)(wsg + p*AA + a);
    }
    if (tid < 32)  *(float4*)&v_s[tid*4] = *(const float4*)(v_w + tid*4);
    if (tid < 128) mk_s[tid] = exp_mask[bq*LEN + tid];
    __syncthreads();

    const int p0 = ty * 4;
    float acc[4][4];
    #pragma unroll
    for (int i = 0; i < 4; i++)
        #pragma unroll
        for (int j = 0; j < 4; j++) acc[i][j] = 0.0f;

    for (int a0 = 0; a0 < AA; a0 += 4){
        float4 v4 = *(const float4*)&v_s[a0];
        float4 w[4], u[4];
        #pragma unroll
        for (int i = 0; i < 4; i++) w[i] = *(const float4*)&ws_s[(p0+i)*132 + a0];
        #pragma unroll
        for (int j = 0; j < 4; j++) u[j] = *(const float4*)&uh_s[(tx + 32*j)*132 + a0];
        #pragma unroll
        for (int i = 0; i < 4; i++){
            #pragma unroll
            for (int j = 0; j < 4; j++){
                float s;
                s  = tanh_fast(u[j].x + w[i].x) * v4.x;
                s += tanh_fast(u[j].y + w[i].y) * v4.y;
                s += tanh_fast(u[j].z + w[i].z) * v4.z;
                s += tanh_fast(u[j].w + w[i].w) * v4.w;
                acc[i][j] += s;
            }
        }
    }
    #pragma unroll
    for (int i = 0; i < 4; i++){
        float* er = g_e + (((size_t)(b*PP + p0 + i))*QQ + q) * LEN;
        #pragma unroll
        for (int j = 0; j < 4; j++){
            int t = tx + 32*j;
            er[t] = mk_s[t] ? acc[i][j] : -1.0e9f;
        }
    }
}

// ---------------------------------------------------------------------------
// K4: softmax over rows of 4096 (in-place on g_e). grid = B*P, 256 threads.
// ---------------------------------------------------------------------------
__global__ void __launch_bounds__(256) k_softmax(){
    __shared__ float red[8];
    __shared__ float bcast;
    const int bp  = blockIdx.x;
    float* row = g_e + (size_t)bp * (QQ*LEN);
    const int tid  = threadIdx.x;
    const int lane = tid & 31, warp = tid >> 5;

    float4 v[4];
    #pragma unroll
    for (int i = 0; i < 4; i++) v[i] = *(const float4*)&row[(tid + i*256)*4];

    float mx = -3.0e38f;
    #pragma unroll
    for (int i = 0; i < 4; i++)
        mx = fmaxf(mx, fmaxf(fmaxf(v[i].x, v[i].y), fmaxf(v[i].z, v[i].w)));
    #pragma unroll
    for (int o = 16; o; o >>= 1) mx = fmaxf(mx, __shfl_xor_sync(0xffffffffu, mx, o));
    if (lane == 0) red[warp] = mx;
    __syncthreads();
    if (tid == 0){
        float m = red[0];
        #pragma unroll
        for (int i = 1; i < 8; i++) m = fmaxf(m, red[i]);
        bcast = m;
    }
    __syncthreads();
    mx = bcast;

    float s = 0.0f;
    #pragma unroll
    for (int i = 0; i < 4; i++){
        v[i].x = __expf(v[i].x - mx); v[i].y = __expf(v[i].y - mx);
        v[i].z = __expf(v[i].z - mx); v[i].w = __expf(v[i].w - mx);
        s += v[i].x + v[i].y + v[i].z + v[i].w;
    }
    #pragma unroll
    for (int o = 16; o; o >>= 1) s += __shfl_xor_sync(0xffffffffu, s, o);
    if (lane == 0) red[warp] = s;
    __syncthreads();
    if (tid == 0){
        float t = 0.0f;
        #pragma unroll
        for (int i = 0; i < 8; i++) t += red[i];
        bcast = 1.0f / t;
    }
    __syncthreads();
    const float inv = bcast;
    #pragma unroll
    for (int i = 0; i < 4; i++){
        v[i].x *= inv; v[i].y *= inv; v[i].z *= inv; v[i].w *= inv;
        *(float4*)&row[(tid + i*256)*4] = v[i];
    }
}

// ---------------------------------------------------------------------------
// K5: out[b,q,p,d] = (sum_t a[b,p,q,t] * X[b,q,t,d]) * req_mask[b,p]
// ---------------------------------------------------------------------------
__global__ void __launch_bounds__(256) k_out(const float* __restrict__ X,
                                             const int*   __restrict__ req_mask,
                                             float* __restrict__ out){
    extern __shared__ float smf[];
    float* Xs   = smf;                 // 32*512
    float* a_s  = smf + 32*512;        // 32*132
    float* rm_s = a_s + 32*132;        // 32
    const int q = blockIdx.x, b = blockIdx.y;
    const int tid = threadIdx.x;
    const int tx = tid & 31, ty = tid >> 5;
    const int bq = b*QQ + q;
    const int p0 = ty * 4;

    #pragma unroll
    for (int i = 0; i < 4; i++){
        int idx = tid + i*256;
        int p = idx >> 5;
        int t = (idx & 31) * 4;
        *(float4*)&a_s[p*132 + t] =
            *(const float4*)(g_e + (((size_t)(b*PP + p))*QQ + q)*LEN + t);
    }
    if (tid < 32) rm_s[tid] = (float)req_mask[b*PP + tid];

    unsigned long long acc2[4][8];
    #pragma unroll
    for (int i = 0; i < 4; i++)
        #pragma unroll
        for (int j = 0; j < 8; j++) acc2[i][j] = 0ull;

    const float* Xg = X + (size_t)bq * LEN * DD;
    for (int c = 0; c < 4; c++){
        __syncthreads();
        #pragma unroll
        for (int i = 0; i < 16; i++){
            int idx = tid + i*256;
            int r  = idx >> 7;
            int wv = (idx & 127) * 4;
            *(float4*)&Xs[r*512 + wv] =
                *(const float4*)(Xg + (size_t)(c*32 + r)*DD + wv);
        }
        __syncthreads();
        #pragma unroll
        for (int tt = 0; tt < 32; tt++){
            const int t = c*32 + tt;
            unsigned long long a2[4];
            #pragma unroll
            for (int i = 0; i < 4; i++){
                float av = a_s[(p0+i)*132 + t];
                a2[i] = pk2(av, av);
            }
            #pragma unroll
            for (int j = 0; j < 4; j++){
                ulonglong2 x2 = *(const ulonglong2*)&Xs[tt*512 + (tx + 32*j)*4];
                #pragma unroll
                for (int i = 0; i < 4; i++){
                    acc2[i][2*j]   = fma2(a2[i], x2.x, acc2[i][2*j]);
                    acc2[i][2*j+1] = fma2(a2[i], x2.y, acc2[i][2*j+1]);
                }
            }
        }
    }
    float* og = out + (size_t)bq * PP * DD;
    #pragma unroll
    for (int i = 0; i < 4; i++){
        float r = rm_s[p0 + i];
        #pragma unroll
        for (int j = 0; j < 4; j++){
            float x0,x1,x2,x3;
            upk2(acc2[i][2*j],   x0, x1);
            upk2(acc2[i][2*j+1], x2, x3);
            *(float4*)(og + (size_t)(p0+i)*DD + (tx + 32*j)*4) =
                make_float4(x0*r, x1*r, x2*r, x3*r);
        }
    }
}

// ---------------------------------------------------------------------------
extern "C" void kernel_launch(void* const* d_in, const int* in_sizes, int n_in,
                              void* d_out, int out_size){
    const float* exp_tokens = (const float*)d_in[0];
    const int*   exp_mask   = (const int*)  d_in[1];
    const float* s_j        = (const float*)d_in[2];
    const int*   req_mask   = (const int*)  d_in[3];
    const float* Ws_w       = (const float*)d_in[4];
    const float* Ws_b       = (const float*)d_in[5];
    const float* U_w        = (const float*)d_in[6];
    const float* v_w        = (const float*)d_in[7];
    float* out = (float*)d_out;

    const int smem_score = (128*132 + 32*132 + 128)*4 + 128*4;   // 85504 B
    const int smem_out   = (32*512 + 32*132 + 32)*4;             // 82560 B
    cudaFuncSetAttribute(k_score,  cudaFuncAttributeMaxDynamicSharedMemorySize, smem_score);
    cudaFuncSetAttribute(k_out,    cudaFuncAttributeMaxDynamicSharedMemorySize, smem_out);
    cudaFuncSetAttribute(k_uh_mma, cudaFuncAttributeMaxDynamicSharedMemorySize, UHMMA_SMEM);

    k_ws     <<<BB*PP, 128>>>(s_j, Ws_w, Ws_b);
    k_prep_u <<<(AA*DD)/1024, 256>>>(U_w);
    k_uh_mma <<<(BB*QQ*LEN)/128, 512, UHMMA_SMEM>>>(exp_tokens);
    k_score  <<<dim3(QQ, BB), 256, smem_score>>>(exp_mask, v_w);
    k_softmax<<<BB*PP, 256>>>();
    k_out    <<<dim3(QQ, BB), 256, smem_out>>>(exp_tokens, req_mask, out);
}

// round 5
// speedup vs baseline: 1.5083x; 1.0470x over previous
#include <cuda_runtime.h>
#include <cuda_bf16.h>
#include <cuda_fp16.h>
#include <cstdint>

#define BB  8
#define QQ  32
#define LEN 128
#define DD  512
#define PP  32
#define AA  128

// Scratch (device globals: allocation-free, graph-capturable)
__device__ float g_ws[BB*PP*AA];                 // (B,P,A)
__device__ float g_uh[BB*QQ*LEN*AA];             // (B,Q,LE,A)  16 MB
__device__ float g_e [BB*PP*QQ*LEN];             // (B,P,Q,LE)   4 MB
__device__ __half g_Uh[AA*DD];                   // U hi split (fp16)
__device__ __half g_Ul[AA*DD];                   // U lo split (fp16)

// ---------------------------------------------------------------------------
// helpers
// ---------------------------------------------------------------------------
__device__ __forceinline__ float tanh_fast(float x){
    float y; asm("tanh.approx.f32 %0, %1;" : "=f"(y) : "f"(x)); return y;
}
__device__ __forceinline__ unsigned long long pk2(float lo, float hi){
    unsigned long long r; asm("mov.b64 %0, {%1,%2};" : "=l"(r) : "f"(lo), "f"(hi)); return r;
}
__device__ __forceinline__ void upk2(unsigned long long v, float& lo, float& hi){
    asm("mov.b64 {%0,%1}, %2;" : "=f"(lo), "=f"(hi) : "l"(v));
}
__device__ __forceinline__ unsigned long long fma2(unsigned long long a,
                                                   unsigned long long b,
                                                   unsigned long long c){
    unsigned long long d;
    asm("fma.rn.f32x2 %0, %1, %2, %3;" : "=l"(d) : "l"(a), "l"(b), "l"(c));
    return d;
}
__device__ __forceinline__ uint32_t smem_u32(const void* p){
    uint32_t a;
    asm("{ .reg .u64 t; cvta.to.shared.u64 t, %1; cvt.u32.u64 %0, t; }" : "=r"(a) : "l"(p));
    return a;
}
__device__ __forceinline__ uint32_t h2u(__half2 v){
    return *reinterpret_cast<uint32_t*>(&v);
}
// sm_80+ primitives (valid at target sm_103)
__device__ __forceinline__ void ldsm4(uint32_t* r, uint32_t a){
    asm volatile("ldmatrix.sync.aligned.m8n8.x4.shared.b16 {%0,%1,%2,%3}, [%4];"
        : "=r"(r[0]), "=r"(r[1]), "=r"(r[2]), "=r"(r[3]) : "r"(a));
}
__device__ __forceinline__ void mma_f16(float* c, const uint32_t* a, const uint32_t* b){
    asm volatile("mma.sync.aligned.m16n8k16.row.col.f32.f16.f16.f32 "
        "{%0,%1,%2,%3}, {%4,%5,%6,%7}, {%8,%9}, {%0,%1,%2,%3};"
        : "+f"(c[0]), "+f"(c[1]), "+f"(c[2]), "+f"(c[3])
        : "r"(a[0]), "r"(a[1]), "r"(a[2]), "r"(a[3]), "r"(b[0]), "r"(b[1]));
}
__device__ __forceinline__ void cp16(uint32_t d, const void* s){
    asm volatile("cp.async.cg.shared.global [%0], [%1], 16;" :: "r"(d), "l"(s));
}
#define CP_COMMIT() asm volatile("cp.async.commit_group;" ::: "memory")
#define CP_WAIT0()  asm volatile("cp.async.wait_group 0;" ::: "memory")

// ---------------------------------------------------------------------------
// K0: split U (fp32) into fp16 hi/lo parts. grid=64, block=256.
// ---------------------------------------------------------------------------
__global__ void __launch_bounds__(256) k_prep_u(const float* __restrict__ U){
    int idx = (blockIdx.x * 256 + threadIdx.x) * 4;
    float4 v = *(const float4*)(U + idx);
    __half hx = __float2half(v.x), hy = __float2half(v.y);
    __half hz = __float2half(v.z), hw = __float2half(v.w);
    __half2 h01 = __halves2half2(hx, hy);
    __half2 h23 = __halves2half2(hz, hw);
    __half2 l01 = __floats2half2_rn(v.x - __half2float(hx), v.y - __half2float(hy));
    __half2 l23 = __floats2half2_rn(v.z - __half2float(hz), v.w - __half2float(hw));
    *(__half2*)(g_Uh + idx)     = h01;
    *(__half2*)(g_Uh + idx + 2) = h23;
    *(__half2*)(g_Ul + idx)     = l01;
    *(__half2*)(g_Ul + idx + 2) = l23;
}

// ---------------------------------------------------------------------------
// K1: ws[b,p,a] = dot(s_j[b,p,:], Ws_w[a,:]) + Ws_b[a]
// ---------------------------------------------------------------------------
__global__ void __launch_bounds__(128) k_ws(const float* __restrict__ s_j,
                                            const float* __restrict__ Ws_w,
                                            const float* __restrict__ Ws_b){
    __shared__ float sj[DD];
    const int bp  = blockIdx.x;
    const int tid = threadIdx.x;
    *(float4*)&sj[tid*4] = *(const float4*)(s_j + (size_t)bp*DD + tid*4);
    __syncthreads();
    float acc = 0.0f;
    const float* wr = Ws_w + (size_t)tid*DD;
    #pragma unroll 8
    for (int d = 0; d < DD; d += 4){
        float4 w = *(const float4*)(wr + d);
        float4 s = *(const float4*)&sj[d];
        acc += w.x*s.x + w.y*s.y + w.z*s.z + w.w*s.w;
    }
    g_ws[bp*AA + tid] = acc + Ws_b[tid];
}

// ---------------------------------------------------------------------------
// K2: uh = X(32768x512) @ U^T via mma.sync fp16 (2-term: Xh*Uh + Xh*Ul).
// X->fp16 direct (rel err 2^-12); U split hi/lo fp16 (residual 2^-24).
// CTA: 128(M) x 128(N), 512 threads (4x4 warp grid, 32x32 per warp).
// K chunks of 64, double-buffered; 3 tiles/chunk -> 110.6KB -> 2 CTAs/SM.
// Rows padded to 144B (conflict-free ldmatrix).
// ---------------------------------------------------------------------------
#define XROWB 144                    // padded row bytes (72 fp16)
#define TILEB (128*XROWB)            // 18432 B per operand tile
#define CHUNKB (3*TILEB)             // Xh,Uh,Ul
#define UHMMA_SMEM (2*CHUNKB)        // 110592 B

__global__ void __launch_bounds__(512) k_uh_mma(const float* __restrict__ X){
    extern __shared__ char sm[];
    const uint32_t sb = smem_u32(sm);
    const int tid  = threadIdx.x;
    const int lane = tid & 31, wid = tid >> 5;
    const int warp_m = wid & 3;          // 0..3 -> 32 M rows
    const int warp_n = wid >> 2;         // 0..3 -> 32 N cols
    const int m0 = blockIdx.x * 128;

    float acc[2][4][4];
    #pragma unroll
    for (int a = 0; a < 2; a++)
        #pragma unroll
        for (int b = 0; b < 4; b++)
            #pragma unroll
            for (int c = 0; c < 4; c++) acc[a][b][c] = 0.0f;

    float4 xr[4];

    // ---- prologue: chunk 0 ----
    #pragma unroll
    for (int j = 0; j < 4; j++){
        int idx = tid + j*512;
        int row = idx >> 4, k4 = (idx & 15) * 4;
        xr[j] = *(const float4*)(X + (size_t)(m0+row)*DD + k4);
    }
    #pragma unroll
    for (int j = 0; j < 2; j++){
        int idx = tid + j*512;
        int row = idx >> 3, seg = idx & 7;
        uint32_t off = (uint32_t)row*XROWB + seg*16;
        cp16(sb + TILEB   + off, g_Uh + (size_t)row*DD + seg*8);
        cp16(sb + 2*TILEB + off, g_Ul + (size_t)row*DD + seg*8);
    }
    CP_COMMIT();
    #pragma unroll
    for (int j = 0; j < 4; j++){
        int idx = tid + j*512;
        int row = idx >> 4, k4 = (idx & 15) * 4;
        float4 v = xr[j];
        uint2 h = make_uint2(h2u(__floats2half2_rn(v.x, v.y)),
                             h2u(__floats2half2_rn(v.z, v.w)));
        uint32_t off = (uint32_t)row*XROWB + (uint32_t)k4*2;
        *(uint2*)(sm + off) = h;
    }
    CP_WAIT0();
    __syncthreads();

    // precomputed fragment addresses (relative to tile base)
    const uint32_t a_base = (uint32_t)(warp_m*32 + (lane & 15))*XROWB + ((lane >> 4) << 4);
    const uint32_t b_base = (uint32_t)(warp_n*32 + (lane & 7) + ((lane >> 4) << 3))*XROWB
                          + (((lane >> 3) & 1) << 4);

    for (int c = 0; c < DD/64; c++){
        const uint32_t boff = (uint32_t)(c & 1) * CHUNKB;
        const uint32_t noff = boff ^ CHUNKB;
        const int k0n = (c+1) * 64;
        if (c < 7){
            #pragma unroll
            for (int j = 0; j < 4; j++){
                int idx = tid + j*512;
                int row = idx >> 4, k4 = (idx & 15) * 4;
                xr[j] = *(const float4*)(X + (size_t)(m0+row)*DD + k0n + k4);
            }
            #pragma unroll
            for (int j = 0; j < 2; j++){
                int idx = tid + j*512;
                int row = idx >> 3, seg = idx & 7;
                uint32_t off = (uint32_t)row*XROWB + seg*16;
                cp16(sb + noff + TILEB   + off, g_Uh + (size_t)row*DD + k0n + seg*8);
                cp16(sb + noff + 2*TILEB + off, g_Ul + (size_t)row*DD + k0n + seg*8);
            }
            CP_COMMIT();
        }
        // ---- compute on buf ----
        const uint32_t xh = sb + boff;
        const uint32_t uh = xh + TILEB, ul = xh + 2*TILEB;
        #pragma unroll
        for (int ks = 0; ks < 4; ks++){
            const uint32_t kb = (uint32_t)ks * 32;
            uint32_t ah[2][4];
            ldsm4(ah[0], xh + a_base + kb);
            ldsm4(ah[1], xh + a_base + kb + 16*XROWB);
            uint32_t bh[4][2], bl[4][2];
            #pragma unroll
            for (int g = 0; g < 2; g++){
                uint32_t t0[4], t1[4];
                ldsm4(t0, uh + b_base + kb + (uint32_t)g*16*XROWB);
                ldsm4(t1, ul + b_base + kb + (uint32_t)g*16*XROWB);
                bh[2*g][0]=t0[0]; bh[2*g][1]=t0[1]; bh[2*g+1][0]=t0[2]; bh[2*g+1][1]=t0[3];
                bl[2*g][0]=t1[0]; bl[2*g][1]=t1[1]; bl[2*g+1][0]=t1[2]; bl[2*g+1][1]=t1[3];
            }
            #pragma unroll
            for (int mt = 0; mt < 2; mt++){
                #pragma unroll
                for (int nt = 0; nt < 4; nt++){
                    mma_f16(acc[mt][nt], ah[mt], bh[nt]);
                    mma_f16(acc[mt][nt], ah[mt], bl[nt]);
                }
            }
        }
        if (c < 7){
            #pragma unroll
            for (int j = 0; j < 4; j++){
                int idx = tid + j*512;
                int row = idx >> 4, k4 = (idx & 15) * 4;
                float4 v = xr[j];
                uint2 h = make_uint2(h2u(__floats2half2_rn(v.x, v.y)),
                                     h2u(__floats2half2_rn(v.z, v.w)));
                uint32_t off = noff + (uint32_t)row*XROWB + (uint32_t)k4*2;
                *(uint2*)(sm + off) = h;
            }
            CP_WAIT0();
        }
        __syncthreads();
    }

    // ---- epilogue ----
    const int r = lane >> 2, cp2 = (lane & 3) * 2;
    float* base = g_uh + (size_t)(m0 + warp_m*32) * AA + warp_n*32;
    #pragma unroll
    for (int mt = 0; mt < 2; mt++){
        #pragma unroll
        for (int nt = 0; nt < 4; nt++){
            float* p0 = base + (size_t)(mt*16 + r) * AA + nt*8 + cp2;
            float* p1 = base + (size_t)(mt*16 + r + 8) * AA + nt*8 + cp2;
            *(float2*)p0 = make_float2(acc[mt][nt][0], acc[mt][nt][1]);
            *(float2*)p1 = make_float2(acc[mt][nt][2], acc[mt][nt][3]);
        }
    }
}

// ---------------------------------------------------------------------------
// K3: e[b,p,q,t] = sum_a tanh(uh[b,q,t,a] + ws[b,p,a]) * v[a]  (+mask)
// ---------------------------------------------------------------------------
__global__ void __launch_bounds__(256) k_score(const int*   __restrict__ exp_mask,
                                               const float* __restrict__ v_w){
    extern __shared__ float smf[];
    float* uh_s = smf;                   // 128*132
    float* ws_s = smf + 128*132;         // 32*132
    float* v_s  = ws_s + 32*132;         // 128
    int*   mk_s = (int*)(v_s + 128);     // 128
    const int q = blockIdx.x, b = blockIdx.y;
    const int tid = threadIdx.x;
    const int tx = tid & 31, ty = tid >> 5;
    const int bq = b*QQ + q;

    const float* uhg = g_uh + (size_t)bq * LEN * AA;
    #pragma unroll
    for (int i = 0; i < 16; i++){
        int idx = tid + i*256;
        int t = idx >> 5;
        int a = (idx & 31) * 4;
        *(float4*)&uh_s[t*132 + a] = *(const float4*)(uhg + t*AA + a);
    }
    const float* wsg = g_ws + b * PP * AA;
    #pragma unroll
    for (int i = 0; i < 4; i++){
        int idx = tid + i*256;
        int p = idx >> 5;
        int a = (idx & 31) * 4;
        *(float4*)&ws_s[p*132 + a] = *(const float4*)(wsg + p*AA + a);
    }
    if (tid < 32)  *(float4*)&v_s[tid*4] = *(const float4*)(v_w + tid*4);
    if (tid < 128) mk_s[tid] = exp_mask[bq*LEN + tid];
    __syncthreads();

    const int p0 = ty * 4;
    float acc[4][4];
    #pragma unroll
    for (int i = 0; i < 4; i++)
        #pragma unroll
        for (int j = 0; j < 4; j++) acc[i][j] = 0.0f;

    for (int a0 = 0; a0 < AA; a0 += 4){
        float4 v4 = *(const float4*)&v_s[a0];
        float4 w[4], u[4];
        #pragma unroll
        for (int i = 0; i < 4; i++) w[i] = *(const float4*)&ws_s[(p0+i)*132 + a0];
        #pragma unroll
        for (int j = 0; j < 4; j++) u[j] = *(const float4*)&uh_s[(tx + 32*j)*132 + a0];
        #pragma unroll
        for (int i = 0; i < 4; i++){
            #pragma unroll
            for (int j = 0; j < 4; j++){
                float s;
                s  = tanh_fast(u[j].x + w[i].x) * v4.x;
                s += tanh_fast(u[j].y + w[i].y) * v4.y;
                s += tanh_fast(u[j].z + w[i].z) * v4.z;
                s += tanh_fast(u[j].w + w[i].w) * v4.w;
                acc[i][j] += s;
            }
        }
    }
    #pragma unroll
    for (int i = 0; i < 4; i++){
        float* er = g_e + (((size_t)(b*PP + p0 + i))*QQ + q) * LEN;
        #pragma unroll
        for (int j = 0; j < 4; j++){
            int t = tx + 32*j;
            er[t] = mk_s[t] ? acc[i][j] : -1.0e9f;
        }
    }
}

// ---------------------------------------------------------------------------
// K4: softmax over rows of 4096 (in-place on g_e). grid = B*P, 256 threads.
// ---------------------------------------------------------------------------
__global__ void __launch_bounds__(256) k_softmax(){
    __shared__ float red[8];
    __shared__ float bcast;
    const int bp  = blockIdx.x;
    float* row = g_e + (size_t)bp * (QQ*LEN);
    const int tid  = threadIdx.x;
    const int lane = tid & 31, warp = tid >> 5;

    float4 v[4];
    #pragma unroll
    for (int i = 0; i < 4; i++) v[i] = *(const float4*)&row[(tid + i*256)*4];

    float mx = -3.0e38f;
    #pragma unroll
    for (int i = 0; i < 4; i++)
        mx = fmaxf(mx, fmaxf(fmaxf(v[i].x, v[i].y), fmaxf(v[i].z, v[i].w)));
    #pragma unroll
    for (int o = 16; o; o >>= 1) mx = fmaxf(mx, __shfl_xor_sync(0xffffffffu, mx, o));
    if (lane == 0) red[warp] = mx;
    __syncthreads();
    if (tid == 0){
        float m = red[0];
        #pragma unroll
        for (int i = 1; i < 8; i++) m = fmaxf(m, red[i]);
        bcast = m;
    }
    __syncthreads();
    mx = bcast;

    float s = 0.0f;
    #pragma unroll
    for (int i = 0; i < 4; i++){
        v[i].x = __expf(v[i].x - mx); v[i].y = __expf(v[i].y - mx);
        v[i].z = __expf(v[i].z - mx); v[i].w = __expf(v[i].w - mx);
        s += v[i].x + v[i].y + v[i].z + v[i].w;
    }
    #pragma unroll
    for (int o = 16; o; o >>= 1) s += __shfl_xor_sync(0xffffffffu, s, o);
    if (lane == 0) red[warp] = s;
    __syncthreads();
    if (tid == 0){
        float t = 0.0f;
        #pragma unroll
        for (int i = 0; i < 8; i++) t += red[i];
        bcast = 1.0f / t;
    }
    __syncthreads();
    const float inv = bcast;
    #pragma unroll
    for (int i = 0; i < 4; i++){
        v[i].x *= inv; v[i].y *= inv; v[i].z *= inv; v[i].w *= inv;
        *(float4*)&row[(tid + i*256)*4] = v[i];
    }
}

// ---------------------------------------------------------------------------
// K5: out[b,q,p,d] = (sum_t a[b,p,q,t] * X[b,q,t,d]) * req_mask[b,p]
// ---------------------------------------------------------------------------
__global__ void __launch_bounds__(256) k_out(const float* __restrict__ X,
                                             const int*   __restrict__ req_mask,
                                             float* __restrict__ out){
    extern __shared__ float smf[];
    float* Xs   = smf;                 // 32*512
    float* a_s  = smf + 32*512;        // 32*132
    float* rm_s = a_s + 32*132;        // 32
    const int q = blockIdx.x, b = blockIdx.y;
    const int tid = threadIdx.x;
    const int tx = tid & 31, ty = tid >> 5;
    const int bq = b*QQ + q;
    const int p0 = ty * 4;

    #pragma unroll
    for (int i = 0; i < 4; i++){
        int idx = tid + i*256;
        int p = idx >> 5;
        int t = (idx & 31) * 4;
        *(float4*)&a_s[p*132 + t] =
            *(const float4*)(g_e + (((size_t)(b*PP + p))*QQ + q)*LEN + t);
    }
    if (tid < 32) rm_s[tid] = (float)req_mask[b*PP + tid];

    unsigned long long acc2[4][8];
    #pragma unroll
    for (int i = 0; i < 4; i++)
        #pragma unroll
        for (int j = 0; j < 8; j++) acc2[i][j] = 0ull;

    const float* Xg = X + (size_t)bq * LEN * DD;
    for (int c = 0; c < 4; c++){
        __syncthreads();
        #pragma unroll
        for (int i = 0; i < 16; i++){
            int idx = tid + i*256;
            int r  = idx >> 7;
            int wv = (idx & 127) * 4;
            *(float4*)&Xs[r*512 + wv] =
                *(const float4*)(Xg + (size_t)(c*32 + r)*DD + wv);
        }
        __syncthreads();
        #pragma unroll
        for (int tt = 0; tt < 32; tt++){
            const int t = c*32 + tt;
            unsigned long long a2[4];
            #pragma unroll
            for (int i = 0; i < 4; i++){
                float av = a_s[(p0+i)*132 + t];
                a2[i] = pk2(av, av);
            }
            #pragma unroll
            for (int j = 0; j < 4; j++){
                ulonglong2 x2 = *(const ulonglong2*)&Xs[tt*512 + (tx + 32*j)*4];
                #pragma unroll
                for (int i = 0; i < 4; i++){
                    acc2[i][2*j]   = fma2(a2[i], x2.x, acc2[i][2*j]);
                    acc2[i][2*j+1] = fma2(a2[i], x2.y, acc2[i][2*j+1]);
                }
            }
        }
    }
    float* og = out + (size_t)bq * PP * DD;
    #pragma unroll
    for (int i = 0; i < 4; i++){
        float r = rm_s[p0 + i];
        #pragma unroll
        for (int j = 0; j < 4; j++){
            float x0,x1,x2,x3;
            upk2(acc2[i][2*j],   x0, x1);
            upk2(acc2[i][2*j+1], x2, x3);
            *(float4*)(og + (size_t)(p0+i)*DD + (tx + 32*j)*4) =
                make_float4(x0*r, x1*r, x2*r, x3*r);
        }
    }
}

// ---------------------------------------------------------------------------
extern "C" void kernel_launch(void* const* d_in, const int* in_sizes, int n_in,
                              void* d_out, int out_size){
    const float* exp_tokens = (const float*)d_in[0];
    const int*   exp_mask   = (const int*)  d_in[1];
    const float* s_j        = (const float*)d_in[2];
    const int*   req_mask   = (const int*)  d_in[3];
    const float* Ws_w       = (const float*)d_in[4];
    const float* Ws_b       = (const float*)d_in[5];
    const float* U_w        = (const float*)d_in[6];
    const float* v_w        = (const float*)d_in[7];
    float* out = (float*)d_out;

    const int smem_score = (128*132 + 32*132 + 128)*4 + 128*4;   // 85504 B
    const int smem_out   = (32*512 + 32*132 + 32)*4;             // 82560 B
    cudaFuncSetAttribute(k_score,  cudaFuncAttributeMaxDynamicSharedMemorySize, smem_score);
    cudaFuncSetAttribute(k_out,    cudaFuncAttributeMaxDynamicSharedMemorySize, smem_out);
    cudaFuncSetAttribute(k_uh_mma, cudaFuncAttributeMaxDynamicSharedMemorySize, UHMMA_SMEM);

    k_ws     <<<BB*PP, 128>>>(s_j, Ws_w, Ws_b);
    k_prep_u <<<(AA*DD)/1024, 256>>>(U_w);
    k_uh_mma <<<(BB*QQ*LEN)/128, 512, UHMMA_SMEM>>>(exp_tokens);
    k_score  <<<dim3(QQ, BB), 256, smem_score>>>(exp_mask, v_w);
    k_softmax<<<BB*PP, 256>>>();
    k_out    <<<dim3(QQ, BB), 256, smem_out>>>(exp_tokens, req_mask, out);
}

// round 7
// speedup vs baseline: 1.6340x; 1.0834x over previous
#include <cuda_runtime.h>
#include <cuda_bf16.h>
#include <cuda_fp16.h>
#include <cstdint>

#define BB  8
#define QQ  32
#define LEN 128
#define DD  512
#define PP  32
#define AA  128
#define NBQ (BB*QQ)

// Scratch (device globals: allocation-free, graph-capturable)
__device__ float g_ws[BB*PP*AA];                 // (B,P,A)
__device__ float g_uhc[BB*QQ*LEN*AA];            // compacted uh rows (dense) 16MB
__device__ float g_e [BB*PP*QQ*LEN];             // (B,P,Q,LE)   4 MB
__device__ __half g_Uh[AA*DD];                   // U hi split (fp16)
__device__ __half g_Ul[AA*DD];                   // U lo split (fp16)
__device__ int   g_cnt[NBQ];                     // unmasked count per (b,q)
__device__ int   g_off[NBQ+1];                   // exclusive offsets
__device__ int   g_tloc[NBQ*LEN];                // per-bq local compacted t
__device__ int   g_tidx[NBQ*LEN + 128];          // dense flat rows (bq*128+t), padded
__device__ int   g_nblk[1];                      // #blocks for k_uh

// ---------------------------------------------------------------------------
// helpers
// ---------------------------------------------------------------------------
__device__ __forceinline__ float tanh_fast(float x){
    float y; asm("tanh.approx.f32 %0, %1;" : "=f"(y) : "f"(x)); return y;
}
__device__ __forceinline__ unsigned long long pk2(float lo, float hi){
    unsigned long long r; asm("mov.b64 %0, {%1,%2};" : "=l"(r) : "f"(lo), "f"(hi)); return r;
}
__device__ __forceinline__ void upk2(unsigned long long v, float& lo, float& hi){
    asm("mov.b64 {%0,%1}, %2;" : "=f"(lo), "=f"(hi) : "l"(v));
}
__device__ __forceinline__ unsigned long long fma2(unsigned long long a,
                                                   unsigned long long b,
                                                   unsigned long long c){
    unsigned long long d;
    asm("fma.rn.f32x2 %0, %1, %2, %3;" : "=l"(d) : "l"(a), "l"(b), "l"(c));
    return d;
}
__device__ __forceinline__ uint32_t smem_u32(const void* p){
    uint32_t a;
    asm("{ .reg .u64 t; cvta.to.shared.u64 t, %1; cvt.u32.u64 %0, t; }" : "=r"(a) : "l"(p));
    return a;
}
__device__ __forceinline__ uint32_t h2u(__half2 v){
    return *reinterpret_cast<uint32_t*>(&v);
}
// sm_80+ primitives (valid at target sm_103)
__device__ __forceinline__ void ldsm4(uint32_t* r, uint32_t a){
    asm volatile("ldmatrix.sync.aligned.m8n8.x4.shared.b16 {%0,%1,%2,%3}, [%4];"
        : "=r"(r[0]), "=r"(r[1]), "=r"(r[2]), "=r"(r[3]) : "r"(a));
}
__device__ __forceinline__ void mma_f16(float* c, const uint32_t* a, const uint32_t* b){
    asm volatile("mma.sync.aligned.m16n8k16.row.col.f32.f16.f16.f32 "
        "{%0,%1,%2,%3}, {%4,%5,%6,%7}, {%8,%9}, {%0,%1,%2,%3};"
        : "+f"(c[0]), "+f"(c[1]), "+f"(c[2]), "+f"(c[3])
        : "r"(a[0]), "r"(a[1]), "r"(a[2]), "r"(a[3]), "r"(b[0]), "r"(b[1]));
}
__device__ __forceinline__ void cp16(uint32_t d, const void* s){
    asm volatile("cp.async.cg.shared.global [%0], [%1], 16;" :: "r"(d), "l"(s));
}
#define CP_COMMIT() asm volatile("cp.async.commit_group;" ::: "memory")
#define CP_WAIT0()  asm volatile("cp.async.wait_group 0;" ::: "memory")

// ---------------------------------------------------------------------------
// K0: split U (fp32) into fp16 hi/lo parts. grid=64, block=256.
// ---------------------------------------------------------------------------
__global__ void __launch_bounds__(256) k_prep_u(const float* __restrict__ U){
    int idx = (blockIdx.x * 256 + threadIdx.x) * 4;
    float4 v = *(const float4*)(U + idx);
    __half hx = __float2half(v.x), hy = __float2half(v.y);
    __half hz = __float2half(v.z), hw = __float2half(v.w);
    __half2 h01 = __halves2half2(hx, hy);
    __half2 h23 = __halves2half2(hz, hw);
    __half2 l01 = __floats2half2_rn(v.x - __half2float(hx), v.y - __half2float(hy));
    __half2 l23 = __floats2half2_rn(v.z - __half2float(hz), v.w - __half2float(hw));
    *(__half2*)(g_Uh + idx)     = h01;
    *(__half2*)(g_Uh + idx + 2) = h23;
    *(__half2*)(g_Ul + idx)     = l01;
    *(__half2*)(g_Ul + idx + 2) = l23;
}

// ---------------------------------------------------------------------------
// K1: ws[b,p,a] = dot(s_j[b,p,:], Ws_w[a,:]) + Ws_b[a]
// ---------------------------------------------------------------------------
__global__ void __launch_bounds__(128) k_ws(const float* __restrict__ s_j,
                                            const float* __restrict__ Ws_w,
                                            const float* __restrict__ Ws_b){
    __shared__ float sj[DD];
    const int bp  = blockIdx.x;
    const int tid = threadIdx.x;
    *(float4*)&sj[tid*4] = *(const float4*)(s_j + (size_t)bp*DD + tid*4);
    __syncthreads();
    float acc = 0.0f;
    const float* wr = Ws_w + (size_t)tid*DD;
    #pragma unroll 8
    for (int d = 0; d < DD; d += 4){
        float4 w = *(const float4*)(wr + d);
        float4 s = *(const float4*)&sj[d];
        acc += w.x*s.x + w.y*s.y + w.z*s.z + w.w*s.w;
    }
    g_ws[bp*AA + tid] = acc + Ws_b[tid];
}

// ---------------------------------------------------------------------------
// C1: per (b,q), compact unmasked t into g_tloc + count. grid=256, 128 thr.
// ---------------------------------------------------------------------------
__global__ void __launch_bounds__(128) k_compact1(const int* __restrict__ exp_mask){
    __shared__ int wc[4];
    const int bq = blockIdx.x, tid = threadIdx.x;
    const int lane = tid & 31, w = tid >> 5;
    bool m = exp_mask[bq*LEN + tid] != 0;
    unsigned bal = __ballot_sync(0xffffffffu, m);
    if (lane == 0) wc[w] = __popc(bal);
    __syncthreads();
    int base = 0;
    #pragma unroll
    for (int i = 0; i < 4; i++) if (i < w) base += wc[i];
    int pre = __popc(bal & ((1u << lane) - 1u));
    if (m) g_tloc[bq*LEN + base + pre] = tid;
    if (tid == 0) g_cnt[bq] = wc[0] + wc[1] + wc[2] + wc[3];
}

// ---------------------------------------------------------------------------
// C2: scan counts -> offsets, pad dense list. 1 block, 256 threads.
// ---------------------------------------------------------------------------
__global__ void __launch_bounds__(256) k_scan(){
    __shared__ int s[256];
    const int tid = threadIdx.x;
    int c = g_cnt[tid];
    s[tid] = c;
    __syncthreads();
    #pragma unroll
    for (int o = 1; o < 256; o <<= 1){
        int v = (tid >= o) ? s[tid - o] : 0;
        __syncthreads();
        s[tid] += v;
        __syncthreads();
    }
    g_off[tid + 1] = s[tid];
    if (tid == 0) g_off[0] = 0;
    if (tid == 255){
        int tot = s[255];
        int pad = (tot + 127) & ~127;
        g_nblk[0] = pad >> 7;
        for (int i = tot; i < pad; i++) g_tidx[i] = 0;
    }
}

// ---------------------------------------------------------------------------
// C3: scatter local lists into dense flat-row list. grid=256, 128 thr.
// ---------------------------------------------------------------------------
__global__ void __launch_bounds__(128) k_compact2(){
    const int bq = blockIdx.x, tid = threadIdx.x;
    const int cnt = g_cnt[bq], off = g_off[bq];
    if (tid < cnt) g_tidx[off + tid] = bq*LEN + g_tloc[bq*LEN + tid];
}

// ---------------------------------------------------------------------------
// K2: uh(dense rows) = gather(X) @ U^T via mma.sync fp16 (Xh*Uh + Xh*Ul).
// Grid 256 (early-exit past g_nblk). 128x128 tile, 512 thr, K chunks of 64,
// double-buffered. Rows padded to 144B (conflict-free ldmatrix).
// ---------------------------------------------------------------------------
#define XROWB 144
#define TILEB (128*XROWB)
#define CHUNKB (3*TILEB)
#define UHMMA_SMEM (2*CHUNKB)        // 110592 B

__global__ void __launch_bounds__(512) k_uh_mma(const float* __restrict__ X){
    if (blockIdx.x >= g_nblk[0]) return;
    extern __shared__ char sm[];
    const uint32_t sb = smem_u32(sm);
    const int tid  = threadIdx.x;
    const int lane = tid & 31, wid = tid >> 5;
    const int warp_m = wid & 3;
    const int warp_n = wid >> 2;
    const int m0 = blockIdx.x * 128;

    float acc[2][4][4];
    #pragma unroll
    for (int a = 0; a < 2; a++)
        #pragma unroll
        for (int b = 0; b < 4; b++)
            #pragma unroll
            for (int c = 0; c < 4; c++) acc[a][b][c] = 0.0f;

    // per-thread gather row pointers (row constant across K chunks)
    const float* xp[4];
    uint32_t soff[4];
    #pragma unroll
    for (int j = 0; j < 4; j++){
        int idx = tid + j*512;
        int row = idx >> 4, k4 = (idx & 15) * 4;
        xp[j] = X + (size_t)g_tidx[m0 + row]*DD + k4;
        soff[j] = (uint32_t)row*XROWB + (uint32_t)k4*2;
    }

    float4 xr[4];
    // ---- prologue: chunk 0 ----
    #pragma unroll
    for (int j = 0; j < 4; j++) xr[j] = *(const float4*)(xp[j]);
    #pragma unroll
    for (int j = 0; j < 2; j++){
        int idx = tid + j*512;
        int row = idx >> 3, seg = idx & 7;
        uint32_t off = (uint32_t)row*XROWB + seg*16;
        cp16(sb + TILEB   + off, g_Uh + (size_t)row*DD + seg*8);
        cp16(sb + 2*TILEB + off, g_Ul + (size_t)row*DD + seg*8);
    }
    CP_COMMIT();
    #pragma unroll
    for (int j = 0; j < 4; j++){
        float4 v = xr[j];
        uint2 h = make_uint2(h2u(__floats2half2_rn(v.x, v.y)),
                             h2u(__floats2half2_rn(v.z, v.w)));
        *(uint2*)(sm + soff[j]) = h;
    }
    CP_WAIT0();
    __syncthreads();

    const uint32_t a_base = (uint32_t)(warp_m*32 + (lane & 15))*XROWB + ((lane >> 4) << 4);
    const uint32_t b_base = (uint32_t)(warp_n*32 + (lane & 7) + ((lane >> 4) << 3))*XROWB
                          + (((lane >> 3) & 1) << 4);

    for (int c = 0; c < DD/64; c++){
        const uint32_t boff = (uint32_t)(c & 1) * CHUNKB;
        const uint32_t noff = boff ^ CHUNKB;
        const int k0n = (c+1) * 64;
        if (c < 7){
            #pragma unroll
            for (int j = 0; j < 4; j++) xr[j] = *(const float4*)(xp[j] + k0n);
            #pragma unroll
            for (int j = 0; j < 2; j++){
                int idx = tid + j*512;
                int row = idx >> 3, seg = idx & 7;
                uint32_t off = (uint32_t)row*XROWB + seg*16;
                cp16(sb + noff + TILEB   + off, g_Uh + (size_t)row*DD + k0n + seg*8);
                cp16(sb + noff + 2*TILEB + off, g_Ul + (size_t)row*DD + k0n + seg*8);
            }
            CP_COMMIT();
        }
        const uint32_t xh = sb + boff;
        const uint32_t uh = xh + TILEB, ul = xh + 2*TILEB;
        #pragma unroll
        for (int ks = 0; ks < 4; ks++){
            const uint32_t kb = (uint32_t)ks * 32;
            uint32_t ah[2][4];
            ldsm4(ah[0], xh + a_base + kb);
            ldsm4(ah[1], xh + a_base + kb + 16*XROWB);
            uint32_t bh[4][2], bl[4][2];
            #pragma unroll
            for (int g = 0; g < 2; g++){
                uint32_t t0[4], t1[4];
                ldsm4(t0, uh + b_base + kb + (uint32_t)g*16*XROWB);
                ldsm4(t1, ul + b_base + kb + (uint32_t)g*16*XROWB);
                bh[2*g][0]=t0[0]; bh[2*g][1]=t0[1]; bh[2*g+1][0]=t0[2]; bh[2*g+1][1]=t0[3];
                bl[2*g][0]=t1[0]; bl[2*g][1]=t1[1]; bl[2*g+1][0]=t1[2]; bl[2*g+1][1]=t1[3];
            }
            #pragma unroll
            for (int mt = 0; mt < 2; mt++){
                #pragma unroll
                for (int nt = 0; nt < 4; nt++){
                    mma_f16(acc[mt][nt], ah[mt], bh[nt]);
                    mma_f16(acc[mt][nt], ah[mt], bl[nt]);
                }
            }
        }
        if (c < 7){
            #pragma unroll
            for (int j = 0; j < 4; j++){
                float4 v = xr[j];
                uint2 h = make_uint2(h2u(__floats2half2_rn(v.x, v.y)),
                                     h2u(__floats2half2_rn(v.z, v.w)));
                *(uint2*)(sm + noff + soff[j]) = h;
            }
            CP_WAIT0();
        }
        __syncthreads();
    }

    // ---- epilogue: dense rows ----
    const int r = lane >> 2, cp2 = (lane & 3) * 2;
    float* base = g_uhc + (size_t)(m0 + warp_m*32) * AA + warp_n*32;
    #pragma unroll
    for (int mt = 0; mt < 2; mt++){
        #pragma unroll
        for (int nt = 0; nt < 4; nt++){
            float* p0 = base + (size_t)(mt*16 + r) * AA + nt*8 + cp2;
            float* p1 = base + (size_t)(mt*16 + r + 8) * AA + nt*8 + cp2;
            *(float2*)p0 = make_float2(acc[mt][nt][0], acc[mt][nt][1]);
            *(float2*)p1 = make_float2(acc[mt][nt][2], acc[mt][nt][3]);
        }
    }
}

// ---------------------------------------------------------------------------
// K3: e over compacted slots; masked t written -1e9 directly.
// grid=(Q,B), 256 thr; tile 4p x 4slots; chunk loop uniform per block.
// ---------------------------------------------------------------------------
__global__ void __launch_bounds__(256) k_score(const int*   __restrict__ exp_mask,
                                               const float* __restrict__ v_w){
    extern __shared__ float smf[];
    float* uh_s = smf;                   // 128*132
    float* ws_s = smf + 128*132;         // 32*132
    float* v_s  = ws_s + 32*132;         // 128
    int*   mk_s = (int*)(v_s + 128);     // 128
    int*   ts_s = mk_s + 128;            // 128
    const int q = blockIdx.x, b = blockIdx.y;
    const int tid = threadIdx.x;
    const int tx = tid & 31, ty = tid >> 5;
    const int bq = b*QQ + q;
    const int cnt = g_cnt[bq], off = g_off[bq];
    const int chunks = (cnt + 31) >> 5;

    if (tid < 128){
        mk_s[tid] = exp_mask[bq*LEN + tid];
        ts_s[tid] = (tid < cnt) ? (g_tidx[off + tid] & (LEN-1)) : 0;
    }
    #pragma unroll
    for (int i = 0; i < 16; i++){
        int idx = tid + i*256;
        int t = idx >> 5;
        int a = (idx & 31) * 4;
        float4 val = make_float4(0.f, 0.f, 0.f, 0.f);
        if (t < cnt) val = *(const float4*)(g_uhc + (size_t)(off + t)*AA + a);
        *(float4*)&uh_s[t*132 + a] = val;
    }
    const float* wsg = g_ws + b * PP * AA;
    #pragma unroll
    for (int i = 0; i < 4; i++){
        int idx = tid + i*256;
        int p = idx >> 5;
        int a = (idx & 31) * 4;
        *(float4*)&ws_s[p*132 + a] = *(const float4*)(wsg + p*AA + a);
    }
    if (tid < 32)  *(float4*)&v_s[tid*4] = *(const float4*)(v_w + tid*4);
    __syncthreads();

    const int p0 = ty * 4;
    float acc[4][4];
    #pragma unroll
    for (int i = 0; i < 4; i++)
        #pragma unroll
        for (int j = 0; j < 4; j++) acc[i][j] = 0.0f;

    for (int a0 = 0; a0 < AA; a0 += 4){
        float4 v4 = *(const float4*)&v_s[a0];
        float4 w[4];
        #pragma unroll
        for (int i = 0; i < 4; i++) w[i] = *(const float4*)&ws_s[(p0+i)*132 + a0];
        #pragma unroll
        for (int j = 0; j < 4; j++){
            if (j < chunks){                       // uniform per block
                float4 u = *(const float4*)&uh_s[(tx + 32*j)*132 + a0];
                #pragma unroll
                for (int i = 0; i < 4; i++){
                    float s;
                    s  = tanh_fast(u.x + w[i].x) * v4.x;
                    s += tanh_fast(u.y + w[i].y) * v4.y;
                    s += tanh_fast(u.z + w[i].z) * v4.z;
                    s += tanh_fast(u.w + w[i].w) * v4.w;
                    acc[i][j] += s;
                }
            }
        }
    }
    #pragma unroll
    for (int i = 0; i < 4; i++){
        float* er = g_e + (((size_t)(b*PP + p0 + i))*QQ + q) * LEN;
        #pragma unroll
        for (int j = 0; j < 4; j++){
            int t = tx + 32*j;
            if (!mk_s[t]) er[t] = -1.0e9f;
        }
        #pragma unroll
        for (int j = 0; j < 4; j++){
            if (j < chunks){
                int slot = tx + 32*j;
                if (slot < cnt) er[ts_s[slot]] = acc[i][j];
            }
        }
    }
}

// ---------------------------------------------------------------------------
// K4: softmax over rows of 4096 (in-place on g_e). grid = B*P, 256 threads.
// ---------------------------------------------------------------------------
__global__ void __launch_bounds__(256) k_softmax(){
    __shared__ float red[8];
    __shared__ float bcast;
    const int bp  = blockIdx.x;
    float* row = g_e + (size_t)bp * (QQ*LEN);
    const int tid  = threadIdx.x;
    const int lane = tid & 31, warp = tid >> 5;

    float4 v[4];
    #pragma unroll
    for (int i = 0; i < 4; i++) v[i] = *(const float4*)&row[(tid + i*256)*4];

    float mx = -3.0e38f;
    #pragma unroll
    for (int i = 0; i < 4; i++)
        mx = fmaxf(mx, fmaxf(fmaxf(v[i].x, v[i].y), fmaxf(v[i].z, v[i].w)));
    #pragma unroll
    for (int o = 16; o; o >>= 1) mx = fmaxf(mx, __shfl_xor_sync(0xffffffffu, mx, o));
    if (lane == 0) red[warp] = mx;
    __syncthreads();
    if (tid == 0){
        float m = red[0];
        #pragma unroll
        for (int i = 1; i < 8; i++) m = fmaxf(m, red[i]);
        bcast = m;
    }
    __syncthreads();
    mx = bcast;

    float s = 0.0f;
    #pragma unroll
    for (int i = 0; i < 4; i++){
        v[i].x = __expf(v[i].x - mx); v[i].y = __expf(v[i].y - mx);
        v[i].z = __expf(v[i].z - mx); v[i].w = __expf(v[i].w - mx);
        s += v[i].x + v[i].y + v[i].z + v[i].w;
    }
    #pragma unroll
    for (int o = 16; o; o >>= 1) s += __shfl_xor_sync(0xffffffffu, s, o);
    if (lane == 0) red[warp] = s;
    __syncthreads();
    if (tid == 0){
        float t = 0.0f;
        #pragma unroll
        for (int i = 0; i < 8; i++) t += red[i];
        bcast = 1.0f / t;
    }
    __syncthreads();
    const float inv = bcast;
    #pragma unroll
    for (int i = 0; i < 4; i++){
        v[i].x *= inv; v[i].y *= inv; v[i].z *= inv; v[i].w *= inv;
        *(float4*)&row[(tid + i*256)*4] = v[i];
    }
}

// ---------------------------------------------------------------------------
// K5: out = (sum over unmasked t of a*X) * req_mask. Compacted t-loop.
// ---------------------------------------------------------------------------
__global__ void __launch_bounds__(256) k_out(const float* __restrict__ X,
                                             const int*   __restrict__ req_mask,
                                             float* __restrict__ out){
    extern __shared__ float smf[];
    float* Xs   = smf;                 // 32*512
    float* a_s  = smf + 32*512;        // 32*132
    float* rm_s = a_s + 32*132;        // 32
    int*   ts_o = (int*)(rm_s + 32);   // 128
    const int q = blockIdx.x, b = blockIdx.y;
    const int tid = threadIdx.x;
    const int tx = tid & 31, ty = tid >> 5;
    const int bq = b*QQ + q;
    const int p0 = ty * 4;
    const int cnt = g_cnt[bq], off = g_off[bq];
    const int chunks = (cnt + 31) >> 5;

    if (tid < 128) ts_o[tid] = (tid < cnt) ? (g_tidx[off + tid] & (LEN-1)) : 0;
    if (tid < 32)  rm_s[tid] = (float)req_mask[b*PP + tid];
    __syncthreads();

    // a_s gather: a_s[p][slot] = a at actual t (0 for invalid slots)
    #pragma unroll
    for (int i = 0; i < 16; i++){
        int idx = tid + i*256;
        int p = idx >> 7;
        int slot = idx & 127;
        float av = 0.0f;
        if (slot < cnt)
            av = g_e[(((size_t)(b*PP + p))*QQ + q)*LEN + ts_o[slot]];
        a_s[p*132 + slot] = av;
    }

    unsigned long long acc2[4][8];
    #pragma unroll
    for (int i = 0; i < 4; i++)
        #pragma unroll
        for (int j = 0; j < 8; j++) acc2[i][j] = 0ull;

    for (int c = 0; c < chunks; c++){
        __syncthreads();   // a_s ready (c==0); Xs readers done (c>0)
        #pragma unroll
        for (int i = 0; i < 16; i++){
            int idx = tid + i*256;
            int r  = idx >> 7;
            int wv = (idx & 127) * 4;
            int t  = ts_o[c*32 + r];
            *(float4*)&Xs[r*512 + wv] =
                *(const float4*)(X + ((size_t)bq*LEN + t)*DD + wv);
        }
        __syncthreads();
        #pragma unroll
        for (int tt = 0; tt < 32; tt++){
            const int slot = c*32 + tt;
            unsigned long long a2[4];
            #pragma unroll
            for (int i = 0; i < 4; i++){
                float av = a_s[(p0+i)*132 + slot];
                a2[i] = pk2(av, av);
            }
            #pragma unroll
            for (int j = 0; j < 4; j++){
                ulonglong2 x2 = *(const ulonglong2*)&Xs[tt*512 + (tx + 32*j)*4];
                #pragma unroll
                for (int i = 0; i < 4; i++){
                    acc2[i][2*j]   = fma2(a2[i], x2.x, acc2[i][2*j]);
                    acc2[i][2*j+1] = fma2(a2[i], x2.y, acc2[i][2*j+1]);
                }
            }
        }
    }
    float* og = out + (size_t)bq * PP * DD;
    #pragma unroll
    for (int i = 0; i < 4; i++){
        float r = rm_s[p0 + i];
        #pragma unroll
        for (int j = 0; j < 4; j++){
            float x0,x1,x2,x3;
            upk2(acc2[i][2*j],   x0, x1);
            upk2(acc2[i][2*j+1], x2, x3);
            *(float4*)(og + (size_t)(p0+i)*DD + (tx + 32*j)*4) =
                make_float4(x0*r, x1*r, x2*r, x3*r);
        }
    }
}

// ---------------------------------------------------------------------------
extern "C" void kernel_launch(void* const* d_in, const int* in_sizes, int n_in,
                              void* d_out, int out_size){
    const float* exp_tokens = (const float*)d_in[0];
    const int*   exp_mask   = (const int*)  d_in[1];
    const float* s_j        = (const float*)d_in[2];
    const int*   req_mask   = (const int*)  d_in[3];
    const float* Ws_w       = (const float*)d_in[4];
    const float* Ws_b       = (const float*)d_in[5];
    const float* U_w        = (const float*)d_in[6];
    const float* v_w        = (const float*)d_in[7];
    float* out = (float*)d_out;

    const int smem_score = (128*132 + 32*132 + 128)*4 + 256*4;   // 86016 B
    const int smem_out   = (32*512 + 32*132 + 32)*4 + 128*4;     // 83072 B
    cudaFuncSetAttribute(k_score,  cudaFuncAttributeMaxDynamicSharedMemorySize, smem_score);
    cudaFuncSetAttribute(k_out,    cudaFuncAttributeMaxDynamicSharedMemorySize, smem_out);
    cudaFuncSetAttribute(k_uh_mma, cudaFuncAttributeMaxDynamicSharedMemorySize, UHMMA_SMEM);

    k_ws      <<<BB*PP, 128>>>(s_j, Ws_w, Ws_b);
    k_prep_u  <<<(AA*DD)/1024, 256>>>(U_w);
    k_compact1<<<NBQ, 128>>>(exp_mask);
    k_scan    <<<1, 256>>>();
    k_compact2<<<NBQ, 128>>>();
    k_uh_mma  <<<NBQ, 512, UHMMA_SMEM>>>(exp_tokens);
    k_score   <<<dim3(QQ, BB), 256, smem_score>>>(exp_mask, v_w);
    k_softmax <<<BB*PP, 256>>>();
    k_out     <<<dim3(QQ, BB), 256, smem_out>>>(exp_tokens, req_mask, out);
}